// round 9
// baseline (speedup 1.0000x reference)
#include <cuda_runtime.h>
#include <cuda_bf16.h>
#include <stdint.h>

// Per-tier abs-max accumulators (slots 1..3). Non-negative float bits order
// like uints, so atomicMax on the uint view is an exact float max.
__device__ unsigned int g_absmax[4];

// Column-mapped abs-max over (tw_i * ts_i) for tiers 1..3 (strided rows —
// measured faster than contiguous chunks). 8x unroll -> 8 LDG.128 in flight.
__global__ void absmax3_kernel(const float4* __restrict__ w1,
                               const float4* __restrict__ w2,
                               const float4* __restrict__ w3,
                               const float4* __restrict__ s1,
                               const float4* __restrict__ s2,
                               const float4* __restrict__ s3,
                               int rows1, int rows2, int rows3,
                               int nb1, int nb2, int nb3, int dim4) {
    const int b = blockIdx.x;
    const float4* __restrict__ w;
    const float4* __restrict__ s;
    int rows, nb, bi, slot;
    if (b < nb1)            { w = w1; s = s1; rows = rows1; nb = nb1; bi = b;             slot = 1; }
    else if (b < nb1 + nb2) { w = w2; s = s2; rows = rows2; nb = nb2; bi = b - nb1;       slot = 2; }
    else                    { w = w3; s = s3; rows = rows3; nb = nb3; bi = b - nb1 - nb2; slot = 3; }

    const int c = threadIdx.x;           // blockDim.x == dim4 (256)
    const float4 sc = s[c];

    float m = 0.f;
    int r = bi;
    const int stride = nb;
    for (; r + 7 * stride < rows; r += 8 * stride) {
        float4 a0 = w[(size_t)(r + 0 * stride) * dim4 + c];
        float4 a1 = w[(size_t)(r + 1 * stride) * dim4 + c];
        float4 a2 = w[(size_t)(r + 2 * stride) * dim4 + c];
        float4 a3 = w[(size_t)(r + 3 * stride) * dim4 + c];
        float4 a4 = w[(size_t)(r + 4 * stride) * dim4 + c];
        float4 a5 = w[(size_t)(r + 5 * stride) * dim4 + c];
        float4 a6 = w[(size_t)(r + 6 * stride) * dim4 + c];
        float4 a7 = w[(size_t)(r + 7 * stride) * dim4 + c];
        float m0 = fmaxf(fmaxf(fabsf(a0.x * sc.x), fabsf(a0.y * sc.y)),
                         fmaxf(fabsf(a0.z * sc.z), fabsf(a0.w * sc.w)));
        float m1 = fmaxf(fmaxf(fabsf(a1.x * sc.x), fabsf(a1.y * sc.y)),
                         fmaxf(fabsf(a1.z * sc.z), fabsf(a1.w * sc.w)));
        float m2 = fmaxf(fmaxf(fabsf(a2.x * sc.x), fabsf(a2.y * sc.y)),
                         fmaxf(fabsf(a2.z * sc.z), fabsf(a2.w * sc.w)));
        float m3 = fmaxf(fmaxf(fabsf(a3.x * sc.x), fabsf(a3.y * sc.y)),
                         fmaxf(fabsf(a3.z * sc.z), fabsf(a3.w * sc.w)));
        float m4 = fmaxf(fmaxf(fabsf(a4.x * sc.x), fabsf(a4.y * sc.y)),
                         fmaxf(fabsf(a4.z * sc.z), fabsf(a4.w * sc.w)));
        float m5 = fmaxf(fmaxf(fabsf(a5.x * sc.x), fabsf(a5.y * sc.y)),
                         fmaxf(fabsf(a5.z * sc.z), fabsf(a5.w * sc.w)));
        float m6 = fmaxf(fmaxf(fabsf(a6.x * sc.x), fabsf(a6.y * sc.y)),
                         fmaxf(fabsf(a6.z * sc.z), fabsf(a6.w * sc.w)));
        float m7 = fmaxf(fmaxf(fabsf(a7.x * sc.x), fabsf(a7.y * sc.y)),
                         fmaxf(fabsf(a7.z * sc.z), fabsf(a7.w * sc.w)));
        m = fmaxf(m, fmaxf(fmaxf(fmaxf(m0, m1), fmaxf(m2, m3)),
                           fmaxf(fmaxf(m4, m5), fmaxf(m6, m7))));
    }
    for (; r < rows; r += stride) {
        float4 a = w[(size_t)r * dim4 + c];
        m = fmaxf(m, fmaxf(fmaxf(fabsf(a.x * sc.x), fabsf(a.y * sc.y)),
                           fmaxf(fabsf(a.z * sc.z), fabsf(a.w * sc.w))));
    }

    #pragma unroll
    for (int o = 16; o; o >>= 1)
        m = fmaxf(m, __shfl_xor_sync(0xFFFFFFFFu, m, o));
    __shared__ float sm[32];
    const int lane = threadIdx.x & 31, wid = threadIdx.x >> 5;
    if (lane == 0) sm[wid] = m;
    __syncthreads();
    const int nwarps = blockDim.x >> 5;
    if (wid == 0) {
        m = (lane < nwarps) ? sm[lane] : 0.f;
        #pragma unroll
        for (int o = 16; o; o >>= 1)
            m = fmaxf(m, __shfl_xor_sync(0xFFFFFFFFu, m, o));
        if (lane == 0) atomicMax(&g_absmax[slot], __float_as_uint(m));
    }
}

// Correctly rounded x/s via Markstein 3-FMA (s and r = RN(1/s) precomputed;
// all values here are comfortably normal), then fake-quant.
__device__ __forceinline__ float fq(float x, float s, float r, float mv) {
    float q0 = x * r;
    float e  = fmaf(-s, q0, x);
    float q  = fmaf(e, r, q0);
    return fminf(fmaxf(rintf(q), -mv), mv) * s;
}

// Warp-per-token gather, bulk-store epilogue. Rows arrive via 8 front-batched
// LDG.128 into registers (fastest measured). The quantized row is staged in a
// per-warp 4KB smem buffer with STS.128 (issue-only) and written back with a
// single cp.async.bulk shared->global (kills the 8x STG.128 issue cost).
__global__ __launch_bounds__(256)
void gather_kernel(const int* __restrict__ ids,
                   const float4* __restrict__ tw0,
                   const float4* __restrict__ tw1,
                   const float4* __restrict__ tw2,
                   const float4* __restrict__ tw3,
                   const float4* __restrict__ ts0,
                   const float4* __restrict__ ts1,
                   const float4* __restrict__ ts2,
                   const float4* __restrict__ ts3,
                   float4* __restrict__ out,
                   long b0, long b1, long b2, long vocab, int ntok) {
    __shared__ float4 s_out[8][256];   // 32 KB out staging (4KB per warp)
    __shared__ float4 s_ts[4][256];    // 16 KB scale vectors
    __shared__ float s_scale[4];
    __shared__ float s_rcp[4];

    const int c    = threadIdx.x;
    const int wid  = c >> 5;
    const int lane = c & 31;

    // Stage the four ts scale vectors + per-tier quant params.
    s_ts[0][c] = ts0[c];
    s_ts[1][c] = ts1[c];
    s_ts[2][c] = ts2[c];
    s_ts[3][c] = ts3[c];
    if (c < 3) {
        const int t = c + 1;
        const float mvq = (t == 1) ? 127.f : (t == 2) ? 31.f : 7.f;
        float sca = fmaxf(__uint_as_float(g_absmax[t]), 1e-8f) / mvq;  // RN div
        s_scale[t] = sca;
        s_rcp[t] = __frcp_rn(sca);   // RN reciprocal -> exact Markstein seed
    }
    if (c == 3) { s_scale[0] = 1.f; s_rcp[0] = 1.f; }

    const int tok = blockIdx.x * 8 + wid;

    // Warp-uniform token resolution (clamped so OOB degrades safely).
    long id = 0;
    if (tok < ntok) id = (long)__ldg(&ids[tok]);
    if (id < 0) id = 0;
    if (id >= vocab) id = vocab - 1;

    const float4* w; int slot; float mv;
    if (id < b0)      { w = tw0 + (size_t)id * 256;        slot = 0; mv = 1.f; }
    else if (id < b1) { w = tw1 + (size_t)(id - b0) * 256; slot = 1; mv = 127.f; }
    else if (id < b2) { w = tw2 + (size_t)(id - b1) * 256; slot = 2; mv = 31.f; }
    else              { w = tw3 + (size_t)(id - b2) * 256; slot = 3; mv = 7.f; }

    // Front-batch the whole row: 8 LDG.128, contiguous 512B chunks.
    float4 v[8];
    #pragma unroll
    for (int i = 0; i < 8; i++) v[i] = w[lane + 32 * i];

    __syncthreads();   // smem staging visible (overlapped with row loads)

    const float scale = s_scale[slot];
    const float rcp   = s_rcp[slot];

    #pragma unroll
    for (int i = 0; i < 8; i++) {
        const float4 sc = s_ts[slot][lane + 32 * i];   // LDS.128, conflict-free
        float4 x = v[i];
        x.x *= sc.x; x.y *= sc.y; x.z *= sc.z; x.w *= sc.w;
        if (slot > 0) {      // warp-uniform branch
            x.x = fq(x.x, scale, rcp, mv);
            x.y = fq(x.y, scale, rcp, mv);
            x.z = fq(x.z, scale, rcp, mv);
            x.w = fq(x.w, scale, rcp, mv);
        }
        s_out[wid][lane + 32 * i] = x;                 // STS.128, issue-only
    }

    __syncwarp();      // all lanes' STS done before lane 0 hands off to bulk DMA

    if (lane == 0 && tok < ntok) {
        asm volatile("fence.proxy.async.shared::cta;" ::: "memory");
        uint32_t saddr = (uint32_t)__cvta_generic_to_shared(&s_out[wid][0]);
        void* gptr = (void*)(out + (size_t)tok * 256);
        asm volatile("cp.async.bulk.global.shared::cta.bulk_group [%0], [%1], %2;"
                     :: "l"(gptr), "r"(saddr), "r"(4096) : "memory");
        asm volatile("cp.async.bulk.commit_group;" ::: "memory");
        asm volatile("cp.async.bulk.wait_group 0;" ::: "memory");
    }
}

extern "C" void kernel_launch(void* const* d_in, const int* in_sizes, int n_in,
                              void* d_out, int out_size) {
    const int*   ids = (const int*)d_in[0];
    const float* tw0 = (const float*)d_in[1];
    const float* tw1 = (const float*)d_in[2];
    const float* tw2 = (const float*)d_in[3];
    const float* tw3 = (const float*)d_in[4];
    const float* ts0 = (const float*)d_in[5];
    const float* ts1 = (const float*)d_in[6];
    const float* ts2 = (const float*)d_in[7];
    const float* ts3 = (const float*)d_in[8];

    const int dim  = in_sizes[5];          // ts0 element count = embedding dim
    const int dim4 = dim / 4;
    const int ntok = in_sizes[0];

    const int r0 = in_sizes[1] / dim;      // tier row counts
    const int r1 = in_sizes[2] / dim;
    const int r2 = in_sizes[3] / dim;
    const int r3 = in_sizes[4] / dim;
    const long b0 = r0;                    // cumulative id boundaries
    const long b1 = b0 + r1;
    const long b2 = b1 + r2;
    const long vocab = b2 + r3;

    // ~16 rows per block per tier, strided interleave (tail via loop).
    const int nb1 = (r1 + 15) / 16;
    const int nb2 = (r2 + 15) / 16;
    const int nb3 = (r3 + 15) / 16;

    void* absmax_addr = nullptr;
    cudaGetSymbolAddress(&absmax_addr, g_absmax);
    cudaMemsetAsync(absmax_addr, 0, 4 * sizeof(unsigned int));

    absmax3_kernel<<<nb1 + nb2 + nb3, dim4>>>(
        (const float4*)tw1, (const float4*)tw2, (const float4*)tw3,
        (const float4*)ts1, (const float4*)ts2, (const float4*)ts3,
        r1, r2, r3, nb1, nb2, nb3, dim4);

    const int nblk = (ntok + 7) / 8;       // one warp per token, 8 per block
    gather_kernel<<<nblk, 256>>>(
        ids,
        (const float4*)tw0, (const float4*)tw1, (const float4*)tw2, (const float4*)tw3,
        (const float4*)ts0, (const float4*)ts1, (const float4*)ts2, (const float4*)ts3,
        (float4*)d_out, b0, b1, b2, vocab, ntok);
}

// round 10
// speedup vs baseline: 1.0900x; 1.0900x over previous
#include <cuda_runtime.h>
#include <cuda_bf16.h>
#include <stdint.h>

// Per-block partial maxima (grid is at most 1024 blocks).
__device__ float g_partial[1024];

// Grid barrier state. g_bar_gen is monotonically increasing across graph
// replays (never reset); g_bar_count returns to 0 inside each barrier.
__device__ unsigned int g_bar_count;
__device__ volatile unsigned int g_bar_gen;

// Correctly rounded x/s via Markstein 3-FMA (s and r = RN(1/s) precomputed;
// all values here are comfortably normal), then fake-quant.
__device__ __forceinline__ float fq(float x, float s, float r, float mv) {
    float q0 = x * r;
    float e  = fmaf(-s, q0, x);
    float q  = fmaf(e, r, q0);
    return fminf(fmaxf(rintf(q), -mv), mv) * s;
}

template <bool STREAM>
__device__ __forceinline__ float4 ldrow(const float4* p) {
    if (STREAM) return __ldcs(p);   // evict-first: don't pollute L2
    return __ldg(p);
}

// Abs-max scan over one tier (strided rows, 8x unroll -> 8 LDG.128 in flight).
// Returns this thread's running max of |w*s| over its column c.
template <bool STREAM>
__device__ float absmax_scan(const float4* __restrict__ w, float4 sc,
                             int rows, int stride, int bi, int c) {
    float m = 0.f;
    int r = bi;
    for (; r + 7 * stride < rows; r += 8 * stride) {
        float4 a0 = ldrow<STREAM>(w + (size_t)(r + 0 * stride) * 256 + c);
        float4 a1 = ldrow<STREAM>(w + (size_t)(r + 1 * stride) * 256 + c);
        float4 a2 = ldrow<STREAM>(w + (size_t)(r + 2 * stride) * 256 + c);
        float4 a3 = ldrow<STREAM>(w + (size_t)(r + 3 * stride) * 256 + c);
        float4 a4 = ldrow<STREAM>(w + (size_t)(r + 4 * stride) * 256 + c);
        float4 a5 = ldrow<STREAM>(w + (size_t)(r + 5 * stride) * 256 + c);
        float4 a6 = ldrow<STREAM>(w + (size_t)(r + 6 * stride) * 256 + c);
        float4 a7 = ldrow<STREAM>(w + (size_t)(r + 7 * stride) * 256 + c);
        float m0 = fmaxf(fmaxf(fabsf(a0.x * sc.x), fabsf(a0.y * sc.y)),
                         fmaxf(fabsf(a0.z * sc.z), fabsf(a0.w * sc.w)));
        float m1 = fmaxf(fmaxf(fabsf(a1.x * sc.x), fabsf(a1.y * sc.y)),
                         fmaxf(fabsf(a1.z * sc.z), fabsf(a1.w * sc.w)));
        float m2 = fmaxf(fmaxf(fabsf(a2.x * sc.x), fabsf(a2.y * sc.y)),
                         fmaxf(fabsf(a2.z * sc.z), fabsf(a2.w * sc.w)));
        float m3 = fmaxf(fmaxf(fabsf(a3.x * sc.x), fabsf(a3.y * sc.y)),
                         fmaxf(fabsf(a3.z * sc.z), fabsf(a3.w * sc.w)));
        float m4 = fmaxf(fmaxf(fabsf(a4.x * sc.x), fabsf(a4.y * sc.y)),
                         fmaxf(fabsf(a4.z * sc.z), fabsf(a4.w * sc.w)));
        float m5 = fmaxf(fmaxf(fabsf(a5.x * sc.x), fabsf(a5.y * sc.y)),
                         fmaxf(fabsf(a5.z * sc.z), fabsf(a5.w * sc.w)));
        float m6 = fmaxf(fmaxf(fabsf(a6.x * sc.x), fabsf(a6.y * sc.y)),
                         fmaxf(fabsf(a6.z * sc.z), fabsf(a6.w * sc.w)));
        float m7 = fmaxf(fmaxf(fabsf(a7.x * sc.x), fabsf(a7.y * sc.y)),
                         fmaxf(fabsf(a7.z * sc.z), fabsf(a7.w * sc.w)));
        m = fmaxf(m, fmaxf(fmaxf(fmaxf(m0, m1), fmaxf(m2, m3)),
                           fmaxf(fmaxf(m4, m5), fmaxf(m6, m7))));
    }
    for (; r < rows; r += stride) {
        float4 a = ldrow<STREAM>(w + (size_t)r * 256 + c);
        m = fmaxf(m, fmaxf(fmaxf(fabsf(a.x * sc.x), fabsf(a.y * sc.y)),
                           fmaxf(fabsf(a.z * sc.z), fabsf(a.w * sc.w))));
    }
    return m;
}

// Fused persistent kernel: phase 1 absmax -> grid barrier -> phase 2 gather.
// Grid MUST be co-resident (host launches 4 blocks per SM; launch_bounds
// guarantees occupancy >= 4).
__global__ __launch_bounds__(256, 4)
void fused_kernel(const int* __restrict__ ids,
                  const float4* __restrict__ tw0,
                  const float4* __restrict__ tw1,
                  const float4* __restrict__ tw2,
                  const float4* __restrict__ tw3,
                  const float4* __restrict__ ts0,
                  const float4* __restrict__ ts1,
                  const float4* __restrict__ ts2,
                  const float4* __restrict__ ts3,
                  float4* __restrict__ out,
                  int rows1, int rows2, int rows3,
                  int nb1, int nb2,
                  long b0, long b1, long b2, long vocab, int ntok) {
    __shared__ float4 s_ts[4][256];            // 16 KB scale vectors
    __shared__ float s_scale[4], s_rcp[4];
    __shared__ unsigned int s_max[3];
    __shared__ float sm[8];

    const int c    = threadIdx.x;
    const int wid  = c >> 5;
    const int lane = c & 31;
    const int nblk = gridDim.x;

    // Stage the four ts scale vectors (used by phase 1 tier selection too).
    s_ts[0][c] = ts0[c];
    s_ts[1][c] = ts1[c];
    s_ts[2][c] = ts2[c];
    s_ts[3][c] = ts3[c];
    if (c < 3) s_max[c] = 0u;
    __syncthreads();

    // ---------------- Phase 1: abs-max over tiers 1..3 ----------------
    const int b = blockIdx.x;
    float m;
    if (b < nb1) {
        m = absmax_scan<false>(tw1, s_ts[1][c], rows1, nb1, b, c);
    } else if (b < nb1 + nb2) {
        m = absmax_scan<false>(tw2, s_ts[2][c], rows2, nb2, b - nb1, c);
    } else {
        // tier 3 (doesn't fit L2): streaming loads keep tiers 1/2 resident
        m = absmax_scan<true>(tw3, s_ts[3][c], rows3, nblk - nb1 - nb2,
                              b - nb1 - nb2, c);
    }

    #pragma unroll
    for (int o = 16; o; o >>= 1)
        m = fmaxf(m, __shfl_xor_sync(0xFFFFFFFFu, m, o));
    if (lane == 0) sm[wid] = m;
    __syncthreads();
    if (c == 0) {
        #pragma unroll
        for (int i = 1; i < 8; i++) m = fmaxf(m, sm[i]);
        g_partial[b] = m;
        __threadfence();            // partial visible before barrier arrival
    }
    __syncthreads();

    // ---------------- Grid barrier (graph-replay safe) ----------------
    if (c == 0) {
        unsigned int gen = g_bar_gen;
        if (atomicAdd(&g_bar_count, 1) == (unsigned int)nblk - 1) {
            g_bar_count = 0;        // all arrived; safe to reset
            __threadfence();
            atomicAdd((unsigned int*)&g_bar_gen, 1);
        } else {
            while (g_bar_gen == gen) __nanosleep(64);
        }
    }
    __syncthreads();

    // ------------- Phase 1.5: reduce partials -> scale/rcp -------------
    for (int t = c; t < nblk; t += 256) {
        float p = __ldcg(&g_partial[t]);    // L2-coherent read
        int seg = (t < nb1) ? 0 : (t < nb1 + nb2) ? 1 : 2;
        atomicMax(&s_max[seg], __float_as_uint(p));
    }
    __syncthreads();
    if (c < 3) {
        const float mvq = (c == 0) ? 127.f : (c == 1) ? 31.f : 7.f;
        float sca = fmaxf(__uint_as_float(s_max[c]), 1e-8f) / mvq;  // RN div
        s_scale[c + 1] = sca;
        s_rcp[c + 1] = __frcp_rn(sca);  // RN reciprocal -> exact Markstein seed
    }
    if (c == 3) { s_scale[0] = 1.f; s_rcp[0] = 1.f; }
    __syncthreads();

    // ---------------- Phase 2: warp-per-token gather ----------------
    const int ngroups = (ntok + 7) / 8;
    for (int g = blockIdx.x; g < ngroups; g += nblk) {
        const int tok = g * 8 + wid;

        long id = 0;
        if (tok < ntok) id = (long)__ldg(&ids[tok]);   // warp-uniform
        if (id < 0) id = 0;
        if (id >= vocab) id = vocab - 1;

        const float4* w; int slot; float mv;
        if (id < b0)      { w = tw0 + (size_t)id * 256;        slot = 0; mv = 1.f; }
        else if (id < b1) { w = tw1 + (size_t)(id - b0) * 256; slot = 1; mv = 127.f; }
        else if (id < b2) { w = tw2 + (size_t)(id - b1) * 256; slot = 2; mv = 31.f; }
        else              { w = tw3 + (size_t)(id - b2) * 256; slot = 3; mv = 7.f; }

        // Front-batch the whole 4KB row: 8 LDG.128, contiguous 512B chunks.
        float4 v[8];
        #pragma unroll
        for (int i = 0; i < 8; i++) v[i] = __ldg(w + lane + 32 * i);

        const float scale = s_scale[slot];
        const float rcp   = s_rcp[slot];
        if (tok >= ntok) continue;
        float4* o = out + (size_t)tok * 256;

        #pragma unroll
        for (int i = 0; i < 8; i++) {
            const float4 sc = s_ts[slot][lane + 32 * i];  // LDS.128, no conflict
            float4 x = v[i];
            x.x *= sc.x; x.y *= sc.y; x.z *= sc.z; x.w *= sc.w;
            if (slot > 0) {   // warp-uniform branch
                x.x = fq(x.x, scale, rcp, mv);
                x.y = fq(x.y, scale, rcp, mv);
                x.z = fq(x.z, scale, rcp, mv);
                x.w = fq(x.w, scale, rcp, mv);
            }
            __stcs(o + lane + 32 * i, x);   // streaming store: no L2 pollution
        }
    }
}

extern "C" void kernel_launch(void* const* d_in, const int* in_sizes, int n_in,
                              void* d_out, int out_size) {
    const int*   ids = (const int*)d_in[0];
    const float* tw0 = (const float*)d_in[1];
    const float* tw1 = (const float*)d_in[2];
    const float* tw2 = (const float*)d_in[3];
    const float* tw3 = (const float*)d_in[4];
    const float* ts0 = (const float*)d_in[5];
    const float* ts1 = (const float*)d_in[6];
    const float* ts2 = (const float*)d_in[7];
    const float* ts3 = (const float*)d_in[8];

    const int dim  = in_sizes[5];          // ts0 element count = embedding dim
    const int ntok = in_sizes[0];

    const int r0 = in_sizes[1] / dim;      // tier row counts
    const int r1 = in_sizes[2] / dim;
    const int r2 = in_sizes[3] / dim;
    const int r3 = in_sizes[4] / dim;
    const long b0 = r0;                    // cumulative id boundaries
    const long b1 = b0 + r1;
    const long b2 = b1 + r2;
    const long vocab = b2 + r3;

    // Co-resident grid: 4 blocks per SM (guaranteed by launch_bounds(256,4)).
    int sm_count = 0;
    cudaDeviceGetAttribute(&sm_count, cudaDevAttrMultiProcessorCount, 0);
    int nblk = 4 * sm_count;
    if (nblk > 1024) nblk = 1024;          // g_partial capacity

    // Proportional tier split of the grid.
    const long total = (long)r1 + r2 + r3;
    int nb1 = (int)((long)nblk * r1 / total); if (nb1 < 1) nb1 = 1;
    int nb2 = (int)((long)nblk * r2 / total); if (nb2 < 1) nb2 = 1;
    if (nb1 + nb2 > nblk - 1) { nb1 = 1; nb2 = 1; }   // defensive

    fused_kernel<<<nblk, 256>>>(
        ids,
        (const float4*)tw0, (const float4*)tw1, (const float4*)tw2, (const float4*)tw3,
        (const float4*)ts0, (const float4*)ts1, (const float4*)ts2, (const float4*)ts3,
        (float4*)d_out,
        r1, r2, r3, nb1, nb2,
        b0, b1, b2, vocab, ntok);
}

// round 11
// speedup vs baseline: 1.1195x; 1.0271x over previous
#include <cuda_runtime.h>
#include <cuda_bf16.h>
#include <stdint.h>

// Per-block partial maxima (grid is at most 1024 blocks).
__device__ float g_partial[1024];

// Grid barrier state. g_bar_gen is monotonically increasing across graph
// replays (never reset); g_bar_count returns to 0 inside each barrier.
__device__ unsigned int g_bar_count;
__device__ volatile unsigned int g_bar_gen;

// Correctly rounded x/s via Markstein 3-FMA (s and r = RN(1/s) precomputed;
// all values here are comfortably normal), then fake-quant.
__device__ __forceinline__ float fq(float x, float s, float r, float mv) {
    float q0 = x * r;
    float e  = fmaf(-s, q0, x);
    float q  = fmaf(e, r, q0);
    return fminf(fmaxf(rintf(q), -mv), mv) * s;
}

__device__ __forceinline__ void cp_async16(void* smem_dst, const void* gmem_src) {
    uint32_t d = (uint32_t)__cvta_generic_to_shared(smem_dst);
    asm volatile("cp.async.cg.shared.global [%0], [%1], 16;" :: "r"(d), "l"(gmem_src));
}

template <bool STREAM>
__device__ __forceinline__ float4 ldrow(const float4* p) {
    if (STREAM) return __ldcs(p);   // evict-first: don't pollute L2
    return __ldg(p);
}

// Abs-max scan over one tier (strided rows, 8x unroll -> 8 LDG.128 in flight).
template <bool STREAM>
__device__ float absmax_scan(const float4* __restrict__ w, float4 sc,
                             int rows, int stride, int bi, int c) {
    float m = 0.f;
    int r = bi;
    for (; r + 7 * stride < rows; r += 8 * stride) {
        float4 a0 = ldrow<STREAM>(w + (size_t)(r + 0 * stride) * 256 + c);
        float4 a1 = ldrow<STREAM>(w + (size_t)(r + 1 * stride) * 256 + c);
        float4 a2 = ldrow<STREAM>(w + (size_t)(r + 2 * stride) * 256 + c);
        float4 a3 = ldrow<STREAM>(w + (size_t)(r + 3 * stride) * 256 + c);
        float4 a4 = ldrow<STREAM>(w + (size_t)(r + 4 * stride) * 256 + c);
        float4 a5 = ldrow<STREAM>(w + (size_t)(r + 5 * stride) * 256 + c);
        float4 a6 = ldrow<STREAM>(w + (size_t)(r + 6 * stride) * 256 + c);
        float4 a7 = ldrow<STREAM>(w + (size_t)(r + 7 * stride) * 256 + c);
        float m0 = fmaxf(fmaxf(fabsf(a0.x * sc.x), fabsf(a0.y * sc.y)),
                         fmaxf(fabsf(a0.z * sc.z), fabsf(a0.w * sc.w)));
        float m1 = fmaxf(fmaxf(fabsf(a1.x * sc.x), fabsf(a1.y * sc.y)),
                         fmaxf(fabsf(a1.z * sc.z), fabsf(a1.w * sc.w)));
        float m2 = fmaxf(fmaxf(fabsf(a2.x * sc.x), fabsf(a2.y * sc.y)),
                         fmaxf(fabsf(a2.z * sc.z), fabsf(a2.w * sc.w)));
        float m3 = fmaxf(fmaxf(fabsf(a3.x * sc.x), fabsf(a3.y * sc.y)),
                         fmaxf(fabsf(a3.z * sc.z), fabsf(a3.w * sc.w)));
        float m4 = fmaxf(fmaxf(fabsf(a4.x * sc.x), fabsf(a4.y * sc.y)),
                         fmaxf(fabsf(a4.z * sc.z), fabsf(a4.w * sc.w)));
        float m5 = fmaxf(fmaxf(fabsf(a5.x * sc.x), fabsf(a5.y * sc.y)),
                         fmaxf(fabsf(a5.z * sc.z), fabsf(a5.w * sc.w)));
        float m6 = fmaxf(fmaxf(fabsf(a6.x * sc.x), fabsf(a6.y * sc.y)),
                         fmaxf(fabsf(a6.z * sc.z), fabsf(a6.w * sc.w)));
        float m7 = fmaxf(fmaxf(fabsf(a7.x * sc.x), fabsf(a7.y * sc.y)),
                         fmaxf(fabsf(a7.z * sc.z), fabsf(a7.w * sc.w)));
        m = fmaxf(m, fmaxf(fmaxf(fmaxf(m0, m1), fmaxf(m2, m3)),
                           fmaxf(fmaxf(m4, m5), fmaxf(m6, m7))));
    }
    for (; r < rows; r += stride) {
        float4 a = ldrow<STREAM>(w + (size_t)r * 256 + c);
        m = fmaxf(m, fmaxf(fmaxf(fabsf(a.x * sc.x), fabsf(a.y * sc.y)),
                           fmaxf(fabsf(a.z * sc.z), fabsf(a.w * sc.w))));
    }
    return m;
}

// Fused persistent kernel: phase 1 absmax -> grid barrier -> phase 2
// cp.async-pipelined gather. Host launches 4 blocks/SM (co-resident).
__global__ __launch_bounds__(256, 4)
void fused_kernel(const int* __restrict__ ids,
                  const float4* __restrict__ tw0,
                  const float4* __restrict__ tw1,
                  const float4* __restrict__ tw2,
                  const float4* __restrict__ tw3,
                  const float4* __restrict__ ts0,
                  const float4* __restrict__ ts1,
                  const float4* __restrict__ ts2,
                  const float4* __restrict__ ts3,
                  float4* __restrict__ out,
                  int rows1, int rows2, int rows3,
                  int nb1, int nb2,
                  long b0, long b1, long b2, long vocab, int ntok) {
    // Per-warp private double-buffer: 8 warps x 2 stages x 2KB = 32 KB.
    __shared__ float4 s_buf[8][2][128];
    __shared__ float s_scale[4], s_rcp[4];
    __shared__ unsigned int s_max[3];
    __shared__ float sm[8];

    const int c    = threadIdx.x;
    const int wid  = c >> 5;
    const int lane = c & 31;
    const int nblk = gridDim.x;

    if (c < 3) s_max[c] = 0u;
    __syncthreads();

    // ---------------- Phase 1: abs-max over tiers 1..3 ----------------
    const int b = blockIdx.x;
    float m;
    if (b < nb1) {
        m = absmax_scan<false>(tw1, __ldg(ts1 + c), rows1, nb1, b, c);
    } else if (b < nb1 + nb2) {
        m = absmax_scan<false>(tw2, __ldg(ts2 + c), rows2, nb2, b - nb1, c);
    } else {
        // tier 3 (doesn't fit L2): streaming loads keep tiers 1/2 resident
        m = absmax_scan<true>(tw3, __ldg(ts3 + c), rows3, nblk - nb1 - nb2,
                              b - nb1 - nb2, c);
    }

    #pragma unroll
    for (int o = 16; o; o >>= 1)
        m = fmaxf(m, __shfl_xor_sync(0xFFFFFFFFu, m, o));
    if (lane == 0) sm[wid] = m;
    __syncthreads();
    if (c == 0) {
        #pragma unroll
        for (int i = 1; i < 8; i++) m = fmaxf(m, sm[i]);
        g_partial[b] = m;
        __threadfence();            // partial visible before barrier arrival
    }
    __syncthreads();

    // ---------------- Grid barrier (graph-replay safe) ----------------
    if (c == 0) {
        unsigned int gen = g_bar_gen;
        if (atomicAdd(&g_bar_count, 1) == (unsigned int)nblk - 1) {
            g_bar_count = 0;        // all arrived; safe to reset
            __threadfence();
            atomicAdd((unsigned int*)&g_bar_gen, 1);
        } else {
            while (g_bar_gen == gen) __nanosleep(64);
        }
    }
    __syncthreads();

    // ------------- Phase 1.5: reduce partials -> scale/rcp -------------
    for (int t = c; t < nblk; t += 256) {
        float p = __ldcg(&g_partial[t]);
        int seg = (t < nb1) ? 0 : (t < nb1 + nb2) ? 1 : 2;
        atomicMax(&s_max[seg], __float_as_uint(p));
    }
    __syncthreads();
    if (c < 3) {
        const float mvq = (c == 0) ? 127.f : (c == 1) ? 31.f : 7.f;
        float sca = fmaxf(__uint_as_float(s_max[c]), 1e-8f) / mvq;  // RN div
        s_scale[c + 1] = sca;
        s_rcp[c + 1] = __frcp_rn(sca);  // RN reciprocal -> exact Markstein seed
    }
    if (c == 3) { s_scale[0] = 1.f; s_rcp[0] = 1.f; }
    __syncthreads();

    // ------- Phase 2: cp.async-pipelined gather (warp = half-token) -------
    // Group g covers tokens g*4 .. g*4+3; warp wid handles token (wid>>1),
    // half (wid&1) (2KB = 128 float4). Each lane reads back exactly the
    // bytes it copied, so cp.async.wait_group alone orders the pipeline.
    const int tk = wid >> 1;            // token slot within group
    const int h  = (wid & 1) * 128;     // half offset in float4 units
    const int ngroups = (ntok + 3) / 4;

    // Resolve token 'g*4+tk': row pointer (half-adjusted), slot, validity.
    auto resolve = [&](int g, const float4*& wrow, int& slot, bool& valid) {
        const int tok = g * 4 + tk;
        valid = (g < ngroups) && (tok < ntok);
        long id = 0;
        if (valid) id = (long)__ldg(&ids[tok]);    // warp-uniform
        if (id < 0) id = 0;
        if (id >= vocab) id = vocab - 1;
        const float4* w;
        if (id < b0)      { w = tw0 + (size_t)id * 256;        slot = 0; }
        else if (id < b1) { w = tw1 + (size_t)(id - b0) * 256; slot = 1; }
        else if (id < b2) { w = tw2 + (size_t)(id - b1) * 256; slot = 2; }
        else              { w = tw3 + (size_t)(id - b2) * 256; slot = 3; }
        wrow = w + h;
    };

    // Prefetch the first group.
    {
        const float4* wrow; int slot; bool valid;
        resolve(blockIdx.x, wrow, slot, valid);
        if (valid) {
            #pragma unroll
            for (int i = 0; i < 4; i++)
                cp_async16(&s_buf[wid][0][i * 32 + lane], wrow + i * 32 + lane);
        }
        asm volatile("cp.async.commit_group;" ::: "memory");
    }

    int stage = 0;
    for (int g = blockIdx.x; g < ngroups; g += nblk, stage ^= 1) {
        // Prefetch next group into the other stage.
        {
            const float4* wrow; int slot; bool valid;
            resolve(g + nblk, wrow, slot, valid);
            if (valid) {
                #pragma unroll
                for (int i = 0; i < 4; i++)
                    cp_async16(&s_buf[wid][stage ^ 1][i * 32 + lane],
                               wrow + i * 32 + lane);
            }
            asm volatile("cp.async.commit_group;" ::: "memory");
        }

        // Current group's metadata (cheap recompute; id is L1-hot).
        const float4* wrow_unused; int slot; bool valid;
        resolve(g, wrow_unused, slot, valid);
        const float mv    = (slot == 1) ? 127.f : (slot == 2) ? 31.f :
                            (slot == 3) ? 7.f : 1.f;
        const float scale = s_scale[slot];
        const float rcp   = s_rcp[slot];
        const float4* tsp = (slot == 0) ? ts0 : (slot == 1) ? ts1 :
                            (slot == 2) ? ts2 : ts3;

        asm volatile("cp.async.wait_group 1;" ::: "memory");

        if (valid) {
            const int tok = g * 4 + tk;
            float4* o = out + (size_t)tok * 256 + h;
            #pragma unroll
            for (int i = 0; i < 4; i++) {
                float4 x  = s_buf[wid][stage][i * 32 + lane];
                float4 sc = __ldg(tsp + h + i * 32 + lane);   // L1-resident
                x.x *= sc.x; x.y *= sc.y; x.z *= sc.z; x.w *= sc.w;
                if (slot > 0) {   // warp-uniform branch
                    x.x = fq(x.x, scale, rcp, mv);
                    x.y = fq(x.y, scale, rcp, mv);
                    x.z = fq(x.z, scale, rcp, mv);
                    x.w = fq(x.w, scale, rcp, mv);
                }
                __stcs(o + i * 32 + lane, x);   // streaming store
            }
        }
    }
}

extern "C" void kernel_launch(void* const* d_in, const int* in_sizes, int n_in,
                              void* d_out, int out_size) {
    const int*   ids = (const int*)d_in[0];
    const float* tw0 = (const float*)d_in[1];
    const float* tw1 = (const float*)d_in[2];
    const float* tw2 = (const float*)d_in[3];
    const float* tw3 = (const float*)d_in[4];
    const float* ts0 = (const float*)d_in[5];
    const float* ts1 = (const float*)d_in[6];
    const float* ts2 = (const float*)d_in[7];
    const float* ts3 = (const float*)d_in[8];

    const int dim  = in_sizes[5];          // ts0 element count = embedding dim
    const int ntok = in_sizes[0];

    const int r0 = in_sizes[1] / dim;      // tier row counts
    const int r1 = in_sizes[2] / dim;
    const int r2 = in_sizes[3] / dim;
    const int r3 = in_sizes[4] / dim;
    const long b0 = r0;                    // cumulative id boundaries
    const long b1 = b0 + r1;
    const long b2 = b1 + r2;
    const long vocab = b2 + r3;

    // Co-resident grid: 4 blocks per SM (guaranteed by launch_bounds(256,4);
    // smem 32KB/block allows >= 4 blocks/SM).
    int sm_count = 0;
    cudaDeviceGetAttribute(&sm_count, cudaDevAttrMultiProcessorCount, 0);
    int nblk = 4 * sm_count;
    if (nblk > 1024) nblk = 1024;          // g_partial capacity

    // Proportional tier split of the grid.
    const long total = (long)r1 + r2 + r3;
    int nb1 = (int)((long)nblk * r1 / total); if (nb1 < 1) nb1 = 1;
    int nb2 = (int)((long)nblk * r2 / total); if (nb2 < 1) nb2 = 1;
    if (nb1 + nb2 > nblk - 1) { nb1 = 1; nb2 = 1; }   // defensive

    fused_kernel<<<nblk, 256>>>(
        ids,
        (const float4*)tw0, (const float4*)tw1, (const float4*)tw2, (const float4*)tw3,
        (const float4*)ts0, (const float4*)ts1, (const float4*)ts2, (const float4*)ts3,
        (float4*)d_out,
        r1, r2, r3, nb1, nb2,
        b0, b1, b2, vocab, ntok);
}